// round 2
// baseline (speedup 1.0000x reference)
#include <cuda_runtime.h>

// ============================================================================
// VLunchboxMHSA — linear-attention reassociation + packed f32x2 FMA
//
//   K[b,m,h,d]   = Σ_c x[b,m,c] qkv[c, h*128+64+d]              (k1, f32x2, dbuf)
//   KV[b,h,d,l]  = Σ_m K[b,m,h,d] v[m,h,l]                       (k2, f32x2)
//   W2[b,h,d,e]  = SCALE Σ_l KV[b,h,d,l] proj[h*64+l, e]         (k3)
//   Wfin[b,c,e]  = Σ_{h,d} qkv[c, h*128+d] W2[b,h,d,e]           (k4)
//   out[b,n,e]   = Σ_c x[b,n,c] Wfin[b,c,e]                      (k5, f32x2)
// ============================================================================

#define SCALE 0.125f

__device__ float d_K[4 * 2048 * 512];    // [b, m, h*64+d]
__device__ float d_KV[32 * 64 * 64];     // [bh, d, l]
__device__ float d_W2[4 * 512 * 64];     // [b, h*64+d, e]
__device__ float d_Wfin[4 * 512 * 64];   // [b, c, e]

// packed f32x2 helpers
__device__ __forceinline__ void fma2(unsigned long long& d,
                                     unsigned long long a,
                                     unsigned long long b) {
    asm("fma.rn.f32x2 %0, %1, %2, %0;" : "+l"(d) : "l"(a), "l"(b));
}
__device__ __forceinline__ unsigned long long splat2(float f) {
    unsigned long long r;
    unsigned u = __float_as_uint(f);
    asm("mov.b64 %0, {%1, %1};" : "=l"(r) : "r"(u));
    return r;
}

// ---------------------------------------------------------------------------
// k0: zero the atomic-accumulated scratch + output
// ---------------------------------------------------------------------------
__global__ void k0_zero(float* __restrict__ out) {
    int idx = blockIdx.x * blockDim.x + threadIdx.x;
    if (idx < 32 * 64 * 64)  d_KV[idx]   = 0.f;
    if (idx < 4 * 512 * 64)  d_Wfin[idx] = 0.f;
    if (idx < 4 * 2048 * 64) out[idx]    = 0.f;
}

// ---------------------------------------------------------------------------
// k1: K = x @ Wk   (M=8192, N=512, K=512)
//     128x128 tile, 256 threads, 8x8/thread, f32x2 math, double-buffered smem
// ---------------------------------------------------------------------------
__global__ __launch_bounds__(256, 2) void k1_kproj(const float* __restrict__ x,
                                                   const float* __restrict__ qkv) {
    __shared__ __align__(16) float As[2][16][132];  // As[buf][k][m]
    __shared__ __align__(16) float Bs[2][16][128];  // Bs[buf][k][n]

    const int tid = threadIdx.x;
    const int bm = blockIdx.y * 128;
    const int bn = blockIdx.x * 128;
    const int ty = tid >> 4;
    const int tx = tid & 15;

    // global-load index precompute
    const int a_r0  = (tid * 2) >> 2;            // pos = tid*2 + {0,1}
    const int a_c40 = ((tid * 2) & 3) << 2;
    const int a_r1  = (tid * 2 + 1) >> 2;
    const int a_c41 = ((tid * 2 + 1) & 3) << 2;
    const int b_kr0 = tid >> 5;                  // pos = tid, tid+256
    const int b_nc0 = (tid & 31) << 2;
    const int b_kr1 = (tid + 256) >> 5;
    const int b_nc1 = b_nc0;

    const int n0   = bn + b_nc0;
    const int col0 = ((n0 >> 6) << 7) + 64 + (n0 & 63);

    unsigned long long acc[8][4];
#pragma unroll
    for (int i = 0; i < 8; i++)
#pragma unroll
        for (int j = 0; j < 4; j++) acc[i][j] = 0ull;

    float4 ra0, ra1, rb0, rb1;

    // prefetch k0 = 0
    ra0 = *(const float4*)(x + ((size_t)(bm + a_r0) << 9) + a_c40);
    ra1 = *(const float4*)(x + ((size_t)(bm + a_r1) << 9) + a_c41);
    rb0 = *(const float4*)(qkv + ((size_t)b_kr0 << 10) + col0);
    rb1 = *(const float4*)(qkv + ((size_t)b_kr1 << 10) + col0);

    // store into buf 0
    As[0][a_c40 + 0][a_r0] = ra0.x; As[0][a_c40 + 1][a_r0] = ra0.y;
    As[0][a_c40 + 2][a_r0] = ra0.z; As[0][a_c40 + 3][a_r0] = ra0.w;
    As[0][a_c41 + 0][a_r1] = ra1.x; As[0][a_c41 + 1][a_r1] = ra1.y;
    As[0][a_c41 + 2][a_r1] = ra1.z; As[0][a_c41 + 3][a_r1] = ra1.w;
    *(float4*)&Bs[0][b_kr0][b_nc0] = rb0;
    *(float4*)&Bs[0][b_kr1][b_nc1] = rb1;
    __syncthreads();

    for (int k0 = 0; k0 < 512; k0 += 16) {
        const int buf = (k0 >> 4) & 1;
        const bool last = (k0 == 496);
        if (!last) {
            const int kn = k0 + 16;
            ra0 = *(const float4*)(x + ((size_t)(bm + a_r0) << 9) + kn + a_c40);
            ra1 = *(const float4*)(x + ((size_t)(bm + a_r1) << 9) + kn + a_c41);
            rb0 = *(const float4*)(qkv + ((size_t)(kn + b_kr0) << 10) + col0);
            rb1 = *(const float4*)(qkv + ((size_t)(kn + b_kr1) << 10) + col0);
        }

#pragma unroll
        for (int kk = 0; kk < 16; kk++) {
            float a[8];
            *(float4*)(a)     = *(float4*)&As[buf][kk][ty * 8];
            *(float4*)(a + 4) = *(float4*)&As[buf][kk][ty * 8 + 4];
            unsigned long long b2[4];
            *(ulonglong2*)(b2)     = *(ulonglong2*)&Bs[buf][kk][tx * 8];
            *(ulonglong2*)(b2 + 2) = *(ulonglong2*)&Bs[buf][kk][tx * 8 + 4];
#pragma unroll
            for (int i = 0; i < 8; i++) {
                unsigned long long a2 = splat2(a[i]);
#pragma unroll
                for (int j = 0; j < 4; j++) fma2(acc[i][j], a2, b2[j]);
            }
        }

        if (!last) {
            const int nb = buf ^ 1;
            As[nb][a_c40 + 0][a_r0] = ra0.x; As[nb][a_c40 + 1][a_r0] = ra0.y;
            As[nb][a_c40 + 2][a_r0] = ra0.z; As[nb][a_c40 + 3][a_r0] = ra0.w;
            As[nb][a_c41 + 0][a_r1] = ra1.x; As[nb][a_c41 + 1][a_r1] = ra1.y;
            As[nb][a_c41 + 2][a_r1] = ra1.z; As[nb][a_c41 + 3][a_r1] = ra1.w;
            *(float4*)&Bs[nb][b_kr0][b_nc0] = rb0;
            *(float4*)&Bs[nb][b_kr1][b_nc1] = rb1;
            __syncthreads();
        }
    }

#pragma unroll
    for (int i = 0; i < 8; i++) {
        float* dst = d_K + ((size_t)(bm + ty * 8 + i) << 9) + bn + tx * 8;
        float2 p0 = *(float2*)&acc[i][0];
        float2 p1 = *(float2*)&acc[i][1];
        float2 p2 = *(float2*)&acc[i][2];
        float2 p3 = *(float2*)&acc[i][3];
        *(float4*)(dst)     = make_float4(p0.x, p0.y, p1.x, p1.y);
        *(float4*)(dst + 4) = make_float4(p2.x, p2.y, p3.x, p3.y);
    }
}

// ---------------------------------------------------------------------------
// k2: KV[bh] += K[b,mrange,h,:]^T @ v[mrange,h,:]   (split over m, atomicAdd)
// ---------------------------------------------------------------------------
__global__ __launch_bounds__(256) void k2_kv(const float* __restrict__ v) {
    const int bh = blockIdx.x;
    const int b  = bh >> 3, h = bh & 7;
    const int ms = blockIdx.y;

    __shared__ __align__(16) float Ks[16][64];
    __shared__ __align__(16) float Vs[16][64];

    const int tid = threadIdx.x;
    const int td  = (tid >> 4) << 2;
    const int tl  = (tid & 15) << 2;
    const int lr  = tid >> 4;
    const int lc  = (tid & 15) << 2;

    unsigned long long acc[4][2];
#pragma unroll
    for (int i = 0; i < 4; i++) { acc[i][0] = 0ull; acc[i][1] = 0ull; }

    const float* Kb = d_K + (size_t)b * 2048 * 512 + h * 64;
    const float* Vb = v + h * 64;

    for (int m0 = ms * 128; m0 < ms * 128 + 128; m0 += 16) {
        *(float4*)&Ks[lr][lc] = *(const float4*)(Kb + (size_t)(m0 + lr) * 512 + lc);
        *(float4*)&Vs[lr][lc] = *(const float4*)(Vb + (size_t)(m0 + lr) * 512 + lc);
        __syncthreads();
#pragma unroll
        for (int mm = 0; mm < 16; mm++) {
            float kd[4];
            *(float4*)kd = *(float4*)&Ks[mm][td];
            unsigned long long v2[2];
            *(ulonglong2*)v2 = *(ulonglong2*)&Vs[mm][tl];
#pragma unroll
            for (int i = 0; i < 4; i++) {
                unsigned long long a2 = splat2(kd[i]);
                fma2(acc[i][0], a2, v2[0]);
                fma2(acc[i][1], a2, v2[1]);
            }
        }
        __syncthreads();
    }

    float* KVp = d_KV + (size_t)bh * 4096;
#pragma unroll
    for (int i = 0; i < 4; i++)
#pragma unroll
        for (int j = 0; j < 2; j++) {
            float2 p = *(float2*)&acc[i][j];
            atomicAdd(&KVp[(td + i) * 64 + tl + 2 * j],     p.x);
            atomicAdd(&KVp[(td + i) * 64 + tl + 2 * j + 1], p.y);
        }
}

// ---------------------------------------------------------------------------
// k3: W2[b, h*64+d, e] = SCALE * Σ_l KV[bh,d,l] * proj[h*64+l, e]
// ---------------------------------------------------------------------------
__global__ __launch_bounds__(256) void k3_w2(const float* __restrict__ proj) {
    const int bh = blockIdx.x;
    const int b  = bh >> 3, h = bh & 7;

    __shared__ __align__(16) float KVs[64][64];
    __shared__ __align__(16) float Ps[64][64];

    const int tid = threadIdx.x;
#pragma unroll
    for (int i = 0; i < 4; i++) {
        int pos = tid + i * 256;
        int r   = pos >> 4;
        int c   = (pos & 15) << 2;
        *(float4*)&KVs[r][c] = *(const float4*)(d_KV + (size_t)bh * 4096 + r * 64 + c);
        *(float4*)&Ps[r][c]  = *(const float4*)(proj + (size_t)(h * 64 + r) * 64 + c);
    }
    __syncthreads();

    const int td = (tid >> 4) << 2;
    const int te = (tid & 15) << 2;
    unsigned long long acc[4][2];
#pragma unroll
    for (int i = 0; i < 4; i++) { acc[i][0] = 0ull; acc[i][1] = 0ull; }

#pragma unroll 8
    for (int l = 0; l < 64; l++) {
        unsigned long long b2[2];
        *(ulonglong2*)b2 = *(ulonglong2*)&Ps[l][te];
#pragma unroll
        for (int i = 0; i < 4; i++) {
            unsigned long long a2 = splat2(KVs[td + i][l]);
            fma2(acc[i][0], a2, b2[0]);
            fma2(acc[i][1], a2, b2[1]);
        }
    }

#pragma unroll
    for (int i = 0; i < 4; i++) {
        float2 p0 = *(float2*)&acc[i][0];
        float2 p1 = *(float2*)&acc[i][1];
        float* dst = d_W2 + ((size_t)b * 512 + h * 64 + td + i) * 64 + te;
        *(float4*)dst = make_float4(SCALE * p0.x, SCALE * p0.y,
                                    SCALE * p1.x, SCALE * p1.y);
    }
}

// ---------------------------------------------------------------------------
// k4: Wfin[b,c,e] += Σ_j Wq[c,j] W2[b,j,e]   (q-columns gather, atomicAdd)
// ---------------------------------------------------------------------------
__global__ __launch_bounds__(256) void k4_wfin(const float* __restrict__ qkv) {
    const int b  = blockIdx.x;
    const int ct = blockIdx.y;
    const int js = blockIdx.z;

    __shared__ __align__(16) float Aq[16][68];
    __shared__ __align__(16) float Bs[16][64];

    const int tid = threadIdx.x;
    const int tc  = (tid >> 4) << 2;
    const int te  = (tid & 15) << 2;
    unsigned long long acc[4][2];
#pragma unroll
    for (int i = 0; i < 4; i++) { acc[i][0] = 0ull; acc[i][1] = 0ull; }

    for (int j0 = js * 128; j0 < js * 128 + 128; j0 += 16) {
        {
            int r  = tid >> 2;
            int c4 = (tid & 3) << 2;
            int c  = ct * 64 + r;
            int j  = j0 + c4;
            float4 a = *(const float4*)(qkv + ((size_t)c << 10) +
                                        ((j >> 6) << 7) + (j & 63));
            Aq[c4 + 0][r] = a.x; Aq[c4 + 1][r] = a.y;
            Aq[c4 + 2][r] = a.z; Aq[c4 + 3][r] = a.w;
        }
        {
            int jr = tid >> 4;
            int e4 = (tid & 15) << 2;
            *(float4*)&Bs[jr][e4] =
                *(const float4*)(d_W2 + ((size_t)b * 512 + j0 + jr) * 64 + e4);
        }
        __syncthreads();
#pragma unroll
        for (int jj = 0; jj < 16; jj++) {
            float a[4];
            *(float4*)a = *(float4*)&Aq[jj][tc];
            unsigned long long b2[2];
            *(ulonglong2*)b2 = *(ulonglong2*)&Bs[jj][te];
#pragma unroll
            for (int i = 0; i < 4; i++) {
                unsigned long long a2 = splat2(a[i]);
                fma2(acc[i][0], a2, b2[0]);
                fma2(acc[i][1], a2, b2[1]);
            }
        }
        __syncthreads();
    }

#pragma unroll
    for (int i = 0; i < 4; i++)
#pragma unroll
        for (int j = 0; j < 2; j++) {
            float2 p = *(float2*)&acc[i][j];
            float* dst = &d_Wfin[((size_t)b * 512 + ct * 64 + tc + i) * 64 + te + 2 * j];
            atomicAdd(dst,     p.x);
            atomicAdd(dst + 1, p.y);
        }
}

// ---------------------------------------------------------------------------
// k5: out[b,n,e] += Σ_c x[b,n,c] Wfin[b,c,e]   (split-K over c, atomicAdd)
// ---------------------------------------------------------------------------
__global__ __launch_bounds__(256) void k5_out(const float* __restrict__ x,
                                              float* __restrict__ out) {
    const int b  = blockIdx.x;
    const int nt = blockIdx.y;
    const int ks = blockIdx.z;

    __shared__ __align__(16) float Xs[16][68];
    __shared__ __align__(16) float Ws[16][64];

    const int tid = threadIdx.x;
    const int tn  = (tid >> 4) << 2;
    const int te  = (tid & 15) << 2;
    unsigned long long acc[4][2];
#pragma unroll
    for (int i = 0; i < 4; i++) { acc[i][0] = 0ull; acc[i][1] = 0ull; }

    for (int c0 = ks * 128; c0 < ks * 128 + 128; c0 += 16) {
        {
            int r  = tid >> 2;
            int c4 = (tid & 3) << 2;
            float4 a = *(const float4*)(x + ((size_t)(b * 2048 + nt * 64 + r) << 9) +
                                        c0 + c4);
            Xs[c4 + 0][r] = a.x; Xs[c4 + 1][r] = a.y;
            Xs[c4 + 2][r] = a.z; Xs[c4 + 3][r] = a.w;
        }
        {
            int cr = tid >> 4;
            int e4 = (tid & 15) << 2;
            *(float4*)&Ws[cr][e4] =
                *(const float4*)(d_Wfin + ((size_t)b * 512 + c0 + cr) * 64 + e4);
        }
        __syncthreads();
#pragma unroll
        for (int cc = 0; cc < 16; cc++) {
            float a[4];
            *(float4*)a = *(float4*)&Xs[cc][tn];
            unsigned long long b2[2];
            *(ulonglong2*)b2 = *(ulonglong2*)&Ws[cc][te];
#pragma unroll
            for (int i = 0; i < 4; i++) {
                unsigned long long a2 = splat2(a[i]);
                fma2(acc[i][0], a2, b2[0]);
                fma2(acc[i][1], a2, b2[1]);
            }
        }
        __syncthreads();
    }

#pragma unroll
    for (int i = 0; i < 4; i++)
#pragma unroll
        for (int j = 0; j < 2; j++) {
            float2 p = *(float2*)&acc[i][j];
            float* dst = &out[((size_t)(b * 2048 + nt * 64 + tn + i)) * 64 + te + 2 * j];
            atomicAdd(dst,     p.x);
            atomicAdd(dst + 1, p.y);
        }
}

// ---------------------------------------------------------------------------
extern "C" void kernel_launch(void* const* d_in, const int* in_sizes, int n_in,
                              void* d_out, int out_size) {
    const float* x    = (const float*)d_in[0];  // [4, 2048, 512]
    const float* v    = (const float*)d_in[1];  // [2048, 8, 64]
    const float* qkv  = (const float*)d_in[2];  // [512, 1024]
    const float* proj = (const float*)d_in[3];  // [512, 64]
    float* out = (float*)d_out;                 // [4, 2048, 64]

    k0_zero<<<2048, 256>>>(out);
    k1_kproj<<<dim3(4, 64), 256>>>(x, qkv);
    k2_kv<<<dim3(32, 16), 256>>>(v);
    k3_w2<<<32, 256>>>(proj);
    k4_wfin<<<dim3(4, 8, 4), 256>>>(qkv);
    k5_out<<<dim3(4, 32, 4), 256>>>(x, out);
}

// round 4
// speedup vs baseline: 1.4399x; 1.4399x over previous
#include <cuda_runtime.h>
#include <cuda_bf16.h>
#include <cstdint>

// ============================================================================
// VLunchboxMHSA — linear-attention reassociation.
// k1 (the only big GEMM, 2.15 G FMA) on tensor cores via portable
// mma.sync.m16n8k16 bf16 with split precision: D = Ah*Bh + Ah*Bl + Al*Bh.
// (tcgen05 is unavailable: harness compiles PTX at compute_103, not 103a.)
// ============================================================================

#define SCALE 0.125f

__device__ float d_K[4 * 2048 * 512];    // [b*m, h*64+d]
__device__ float d_KV[32 * 64 * 64];     // [bh, d, l]
__device__ float d_W2[4 * 512 * 64];     // [b, h*64+d, e]
__device__ float d_Wfin[4 * 512 * 64];   // [b, c, e]

// ---------------- helpers ---------------------------------------------------
__device__ __forceinline__ void mma16816(float* c, const uint32_t* a,
                                         uint32_t b0, uint32_t b1) {
    asm volatile(
        "mma.sync.aligned.m16n8k16.row.col.f32.bf16.bf16.f32 "
        "{%0,%1,%2,%3}, {%4,%5,%6,%7}, {%8,%9}, {%0,%1,%2,%3};"
        : "+f"(c[0]), "+f"(c[1]), "+f"(c[2]), "+f"(c[3])
        : "r"(a[0]), "r"(a[1]), "r"(a[2]), "r"(a[3]), "r"(b0), "r"(b1));
}

// split 8 floats into hi/lo bf16 (4x bf16x2 each)
__device__ __forceinline__ void split8(const float* f, uint4& hi, uint4& lo) {
    uint32_t h[4], l[4];
#pragma unroll
    for (int i = 0; i < 4; i++) {
        float2 p = make_float2(f[2 * i], f[2 * i + 1]);
        __nv_bfloat162 hb = __float22bfloat162_rn(p);
        float2 hr = __bfloat1622float2(hb);
        __nv_bfloat162 lb =
            __float22bfloat162_rn(make_float2(p.x - hr.x, p.y - hr.y));
        h[i] = *(uint32_t*)&hb;
        l[i] = *(uint32_t*)&lb;
    }
    hi = make_uint4(h[0], h[1], h[2], h[3]);
    lo = make_uint4(l[0], l[1], l[2], l[3]);
}

// packed f32x2 helpers (SIMT tail kernels)
__device__ __forceinline__ void fma2(unsigned long long& d,
                                     unsigned long long a,
                                     unsigned long long b) {
    asm("fma.rn.f32x2 %0, %1, %2, %0;" : "+l"(d) : "l"(a), "l"(b));
}
__device__ __forceinline__ unsigned long long splat2(float f) {
    unsigned long long r;
    unsigned u = __float_as_uint(f);
    asm("mov.b64 %0, {%1, %1};" : "=l"(r) : "r"(u));
    return r;
}

// ---------------------------------------------------------------------------
// k0: zero scratch + out;  nop pads keep k1 in the profiled launch slot
// ---------------------------------------------------------------------------
__global__ void k0_zero(float* __restrict__ out) {
    int idx = blockIdx.x * blockDim.x + threadIdx.x;
    if (idx < 32 * 64 * 64)  d_KV[idx]   = 0.f;
    if (idx < 4 * 512 * 64)  d_Wfin[idx] = 0.f;
    if (idx < 4 * 2048 * 64) out[idx]    = 0.f;
}
__global__ void k_nop() {}

// ---------------------------------------------------------------------------
// k1_mma: K = x @ Wk  (M=8192, N=512, K=512), bf16 split-precision tensor core
//   grid (4 n-tiles, 64 m-tiles), 256 thr, CTA tile 128x128, K-chunks of 32
//   warps 4(m) x 2(n): warp tile 32(m) x 64(n) -> 2 m-frags x 8 n-frags
// ---------------------------------------------------------------------------
#define LDA 40   // bf16 elements per smem row (32 + 8 pad) -> conflict-free

__global__ __launch_bounds__(256) void k1_mma(const float* __restrict__ x,
                                              const float* __restrict__ qkv) {
    __shared__ __align__(16) __nv_bfloat16 Ah[128][LDA];
    __shared__ __align__(16) __nv_bfloat16 Al[128][LDA];
    __shared__ __align__(16) __nv_bfloat16 Bh[128][LDA];
    __shared__ __align__(16) __nv_bfloat16 Bl[128][LDA];

    const int tid  = threadIdx.x;
    const int wid  = tid >> 5;
    const int lane = tid & 31;
    const int bm = blockIdx.y * 128;
    const int bn = blockIdx.x * 128;
    const int warp_m = (wid & 3) * 32;
    const int warp_n = (wid >> 2) * 64;
    const int tg = lane >> 2;   // 0..7
    const int tq = lane & 3;    // 0..3

    float acc[2][8][4];
#pragma unroll
    for (int mt = 0; mt < 2; mt++)
#pragma unroll
        for (int nt = 0; nt < 8; nt++)
#pragma unroll
            for (int i = 0; i < 4; i++) acc[mt][nt][i] = 0.f;

    // loader coordinates: each thread owns one (row, 16-wide k-half)
    const int ldr = tid >> 1;            // 0..127
    const int lkb = (tid & 1) * 16;      // 0 or 16
    const float* xp = x + ((size_t)(bm + ldr) << 9);
    const int gn   = bn + ldr;
    const int colB = ((gn >> 6) << 7) + 64 + (gn & 63);   // Wk column in qkv

    for (int kc = 0; kc < 16; kc++) {
        const int k0 = kc * 32;

        // ---- A: x[128][32] -> hi/lo bf16 ----
#pragma unroll
        for (int g = 0; g < 2; g++) {
            float f[8];
            *(float4*)(f)     = *(const float4*)(xp + k0 + lkb + g * 8);
            *(float4*)(f + 4) = *(const float4*)(xp + k0 + lkb + g * 8 + 4);
            uint4 hi, lo;
            split8(f, hi, lo);
            *(uint4*)&Ah[ldr][lkb + g * 8] = hi;
            *(uint4*)&Al[ldr][lkb + g * 8] = lo;
        }
        // ---- B: Wk gather B[n][k] = qkv[k][colB(n)] -> hi/lo bf16 ----
#pragma unroll
        for (int g = 0; g < 2; g++) {
            float f[8];
#pragma unroll
            for (int j = 0; j < 8; j++)
                f[j] = qkv[((size_t)(k0 + lkb + g * 8 + j) << 10) + colB];
            uint4 hi, lo;
            split8(f, hi, lo);
            *(uint4*)&Bh[ldr][lkb + g * 8] = hi;
            *(uint4*)&Bl[ldr][lkb + g * 8] = lo;
        }
        __syncthreads();

        // ---- compute: 2 k16-steps, 3 split passes ----
#pragma unroll
        for (int ks = 0; ks < 2; ks++) {
            const int kk = ks * 16 + tq * 2;
            uint32_t ah[2][4], al[2][4];
#pragma unroll
            for (int mt = 0; mt < 2; mt++) {
                const int m = warp_m + mt * 16 + tg;
                ah[mt][0] = *(uint32_t*)&Ah[m][kk];
                ah[mt][1] = *(uint32_t*)&Ah[m + 8][kk];
                ah[mt][2] = *(uint32_t*)&Ah[m][kk + 8];
                ah[mt][3] = *(uint32_t*)&Ah[m + 8][kk + 8];
                al[mt][0] = *(uint32_t*)&Al[m][kk];
                al[mt][1] = *(uint32_t*)&Al[m + 8][kk];
                al[mt][2] = *(uint32_t*)&Al[m][kk + 8];
                al[mt][3] = *(uint32_t*)&Al[m + 8][kk + 8];
            }
#pragma unroll
            for (int nt = 0; nt < 8; nt++) {
                const int n = warp_n + nt * 8 + tg;
                uint32_t bh0 = *(uint32_t*)&Bh[n][kk];
                uint32_t bh1 = *(uint32_t*)&Bh[n][kk + 8];
                uint32_t bl0 = *(uint32_t*)&Bl[n][kk];
                uint32_t bl1 = *(uint32_t*)&Bl[n][kk + 8];
#pragma unroll
                for (int mt = 0; mt < 2; mt++) {
                    mma16816(acc[mt][nt], ah[mt], bh0, bh1);
                    mma16816(acc[mt][nt], ah[mt], bl0, bl1);
                    mma16816(acc[mt][nt], al[mt], bh0, bh1);
                }
            }
        }
        __syncthreads();
    }

    // ---- epilogue: fragment -> d_K ----
#pragma unroll
    for (int mt = 0; mt < 2; mt++) {
        const int m = bm + warp_m + mt * 16 + tg;
#pragma unroll
        for (int nt = 0; nt < 8; nt++) {
            const int n = bn + warp_n + nt * 8 + tq * 2;
            *(float2*)&d_K[(size_t)m * 512 + n] =
                make_float2(acc[mt][nt][0], acc[mt][nt][1]);
            *(float2*)&d_K[(size_t)(m + 8) * 512 + n] =
                make_float2(acc[mt][nt][2], acc[mt][nt][3]);
        }
    }
}

// ---------------------------------------------------------------------------
// k2: KV[bh] += K[b,mrange,h,:]^T @ v[mrange,h,:]   (split over m, atomicAdd)
// ---------------------------------------------------------------------------
__global__ __launch_bounds__(256) void k2_kv(const float* __restrict__ v) {
    const int bh = blockIdx.x;
    const int b  = bh >> 3, h = bh & 7;
    const int ms = blockIdx.y;

    __shared__ __align__(16) float Ks[16][64];
    __shared__ __align__(16) float Vs[16][64];

    const int tid = threadIdx.x;
    const int td  = (tid >> 4) << 2;
    const int tl  = (tid & 15) << 2;
    const int lr  = tid >> 4;
    const int lc  = (tid & 15) << 2;

    unsigned long long acc[4][2];
#pragma unroll
    for (int i = 0; i < 4; i++) { acc[i][0] = 0ull; acc[i][1] = 0ull; }

    const float* Kb = d_K + (size_t)b * 2048 * 512 + h * 64;
    const float* Vb = v + h * 64;

    for (int m0 = ms * 128; m0 < ms * 128 + 128; m0 += 16) {
        *(float4*)&Ks[lr][lc] = *(const float4*)(Kb + (size_t)(m0 + lr) * 512 + lc);
        *(float4*)&Vs[lr][lc] = *(const float4*)(Vb + (size_t)(m0 + lr) * 512 + lc);
        __syncthreads();
#pragma unroll
        for (int mm = 0; mm < 16; mm++) {
            float kd[4];
            *(float4*)kd = *(float4*)&Ks[mm][td];
            unsigned long long v2[2];
            *(ulonglong2*)v2 = *(ulonglong2*)&Vs[mm][tl];
#pragma unroll
            for (int i = 0; i < 4; i++) {
                unsigned long long a2 = splat2(kd[i]);
                fma2(acc[i][0], a2, v2[0]);
                fma2(acc[i][1], a2, v2[1]);
            }
        }
        __syncthreads();
    }

    float* KVp = d_KV + (size_t)bh * 4096;
#pragma unroll
    for (int i = 0; i < 4; i++)
#pragma unroll
        for (int j = 0; j < 2; j++) {
            float2 p = *(float2*)&acc[i][j];
            atomicAdd(&KVp[(td + i) * 64 + tl + 2 * j],     p.x);
            atomicAdd(&KVp[(td + i) * 64 + tl + 2 * j + 1], p.y);
        }
}

// ---------------------------------------------------------------------------
// k3: W2[b, h*64+d, e] = SCALE * Σ_l KV[bh,d,l] * proj[h*64+l, e]
// ---------------------------------------------------------------------------
__global__ __launch_bounds__(256) void k3_w2(const float* __restrict__ proj) {
    const int bh = blockIdx.x;
    const int b  = bh >> 3, h = bh & 7;

    __shared__ __align__(16) float KVs[64][64];
    __shared__ __align__(16) float Ps[64][64];

    const int tid = threadIdx.x;
#pragma unroll
    for (int i = 0; i < 4; i++) {
        int pos = tid + i * 256;
        int r   = pos >> 4;
        int c   = (pos & 15) << 2;
        *(float4*)&KVs[r][c] = *(const float4*)(d_KV + (size_t)bh * 4096 + r * 64 + c);
        *(float4*)&Ps[r][c]  = *(const float4*)(proj + (size_t)(h * 64 + r) * 64 + c);
    }
    __syncthreads();

    const int td = (tid >> 4) << 2;
    const int te = (tid & 15) << 2;
    unsigned long long acc[4][2];
#pragma unroll
    for (int i = 0; i < 4; i++) { acc[i][0] = 0ull; acc[i][1] = 0ull; }

#pragma unroll 8
    for (int l = 0; l < 64; l++) {
        unsigned long long b2[2];
        *(ulonglong2*)b2 = *(ulonglong2*)&Ps[l][te];
#pragma unroll
        for (int i = 0; i < 4; i++) {
            unsigned long long a2 = splat2(KVs[td + i][l]);
            fma2(acc[i][0], a2, b2[0]);
            fma2(acc[i][1], a2, b2[1]);
        }
    }

#pragma unroll
    for (int i = 0; i < 4; i++) {
        float2 p0 = *(float2*)&acc[i][0];
        float2 p1 = *(float2*)&acc[i][1];
        float* dst = d_W2 + ((size_t)b * 512 + h * 64 + td + i) * 64 + te;
        *(float4*)dst = make_float4(SCALE * p0.x, SCALE * p0.y,
                                    SCALE * p1.x, SCALE * p1.y);
    }
}

// ---------------------------------------------------------------------------
// k4: Wfin[b,c,e] += Σ_j Wq[c,j] W2[b,j,e]   (q-columns gather, atomicAdd)
// ---------------------------------------------------------------------------
__global__ __launch_bounds__(256) void k4_wfin(const float* __restrict__ qkv) {
    const int b  = blockIdx.x;
    const int ct = blockIdx.y;
    const int js = blockIdx.z;

    __shared__ __align__(16) float Aq[16][68];
    __shared__ __align__(16) float Bs[16][64];

    const int tid = threadIdx.x;
    const int tc  = (tid >> 4) << 2;
    const int te  = (tid & 15) << 2;
    unsigned long long acc[4][2];
#pragma unroll
    for (int i = 0; i < 4; i++) { acc[i][0] = 0ull; acc[i][1] = 0ull; }

    for (int j0 = js * 128; j0 < js * 128 + 128; j0 += 16) {
        {
            int r  = tid >> 2;
            int c4 = (tid & 3) << 2;
            int c  = ct * 64 + r;
            int j  = j0 + c4;
            float4 a = *(const float4*)(qkv + ((size_t)c << 10) +
                                        ((j >> 6) << 7) + (j & 63));
            Aq[c4 + 0][r] = a.x; Aq[c4 + 1][r] = a.y;
            Aq[c4 + 2][r] = a.z; Aq[c4 + 3][r] = a.w;
        }
        {
            int jr = tid >> 4;
            int e4 = (tid & 15) << 2;
            *(float4*)&Bs[jr][e4] =
                *(const float4*)(d_W2 + ((size_t)b * 512 + j0 + jr) * 64 + e4);
        }
        __syncthreads();
#pragma unroll
        for (int jj = 0; jj < 16; jj++) {
            float a[4];
            *(float4*)a = *(float4*)&Aq[jj][tc];
            unsigned long long b2[2];
            *(ulonglong2*)b2 = *(ulonglong2*)&Bs[jj][te];
#pragma unroll
            for (int i = 0; i < 4; i++) {
                unsigned long long a2 = splat2(a[i]);
                fma2(acc[i][0], a2, b2[0]);
                fma2(acc[i][1], a2, b2[1]);
            }
        }
        __syncthreads();
    }

#pragma unroll
    for (int i = 0; i < 4; i++)
#pragma unroll
        for (int j = 0; j < 2; j++) {
            float2 p = *(float2*)&acc[i][j];
            float* dst = &d_Wfin[((size_t)b * 512 + ct * 64 + tc + i) * 64 + te + 2 * j];
            atomicAdd(dst,     p.x);
            atomicAdd(dst + 1, p.y);
        }
}

// ---------------------------------------------------------------------------
// k5: out[b,n,e] += Σ_c x[b,n,c] Wfin[b,c,e]   (split-K over c, atomicAdd)
// ---------------------------------------------------------------------------
__global__ __launch_bounds__(256) void k5_out(const float* __restrict__ x,
                                              float* __restrict__ out) {
    const int b  = blockIdx.x;
    const int nt = blockIdx.y;
    const int ks = blockIdx.z;

    __shared__ __align__(16) float Xs[16][68];
    __shared__ __align__(16) float Ws[16][64];

    const int tid = threadIdx.x;
    const int tn  = (tid >> 4) << 2;
    const int te  = (tid & 15) << 2;
    unsigned long long acc[4][2];
#pragma unroll
    for (int i = 0; i < 4; i++) { acc[i][0] = 0ull; acc[i][1] = 0ull; }

    for (int c0 = ks * 128; c0 < ks * 128 + 128; c0 += 16) {
        {
            int r  = tid >> 2;
            int c4 = (tid & 3) << 2;
            float4 a = *(const float4*)(x + ((size_t)(b * 2048 + nt * 64 + r) << 9) +
                                        c0 + c4);
            Xs[c4 + 0][r] = a.x; Xs[c4 + 1][r] = a.y;
            Xs[c4 + 2][r] = a.z; Xs[c4 + 3][r] = a.w;
        }
        {
            int cr = tid >> 4;
            int e4 = (tid & 15) << 2;
            *(float4*)&Ws[cr][e4] =
                *(const float4*)(d_Wfin + ((size_t)b * 512 + c0 + cr) * 64 + e4);
        }
        __syncthreads();
#pragma unroll
        for (int cc = 0; cc < 16; cc++) {
            float a[4];
            *(float4*)a = *(float4*)&Xs[cc][tn];
            unsigned long long b2[2];
            *(ulonglong2*)b2 = *(ulonglong2*)&Ws[cc][te];
#pragma unroll
            for (int i = 0; i < 4; i++) {
                unsigned long long a2 = splat2(a[i]);
                fma2(acc[i][0], a2, b2[0]);
                fma2(acc[i][1], a2, b2[1]);
            }
        }
        __syncthreads();
    }

#pragma unroll
    for (int i = 0; i < 4; i++)
#pragma unroll
        for (int j = 0; j < 2; j++) {
            float2 p = *(float2*)&acc[i][j];
            float* dst = &out[((size_t)(b * 2048 + nt * 64 + tn + i)) * 64 + te + 2 * j];
            atomicAdd(dst,     p.x);
            atomicAdd(dst + 1, p.y);
        }
}

// ---------------------------------------------------------------------------
extern "C" void kernel_launch(void* const* d_in, const int* in_sizes, int n_in,
                              void* d_out, int out_size) {
    const float* x    = (const float*)d_in[0];  // [4, 2048, 512]
    const float* v    = (const float*)d_in[1];  // [2048, 8, 64]
    const float* qkv  = (const float*)d_in[2];  // [512, 1024]
    const float* proj = (const float*)d_in[3];  // [512, 64]
    float* out = (float*)d_out;                 // [4, 2048, 64]

    k0_zero<<<2048, 256>>>(out);
    k_nop<<<1, 32>>>();
    k_nop<<<1, 32>>>();                         // k1_mma -> profiled launch slot
    k1_mma<<<dim3(4, 64), 256>>>(x, qkv);
    k2_kv<<<dim3(32, 16), 256>>>(v);
    k3_w2<<<32, 256>>>(proj);
    k4_wfin<<<dim3(4, 8, 4), 256>>>(qkv);
    k5_out<<<dim3(4, 32, 4), 256>>>(x, out);
}